// round 7
// baseline (speedup 1.0000x reference)
#include <cuda_runtime.h>
#include <cstdint>
#include <cstddef>

#define BB 8
#define CC 64
#define NN 8192
#define MM 2048
#define KK 16
#define FPSM 1433
#define RANDM 615
#define FULLMASK 0xffffffffu

#define STHR 512
#define HALF (NN / 2)        // 4096 points per FPS CTA
#define FPT  (HALF / STHR)   // 8 points per thread
#define FPRS (FPT / 2)       // 4 packed pairs per thread

// ---------------- device scratch (static: no allocations allowed) ----------
__device__ int   g_idx[BB * MM];                 // selected center indices
__device__ int   g_knn[BB * MM * KK];            // knn indices
__device__ float g_xT[(size_t)BB * NN * CC];     // x transposed to [B,N,C]

// ---------------- Threefry-2x32 (exact JAX) --------------------------------
__device__ __forceinline__ uint32_t rotl32(uint32_t v, int d) {
    return (v << d) | (v >> (32 - d));
}

__device__ __forceinline__ void tf2x32(uint32_t k0, uint32_t k1,
                                       uint32_t x0, uint32_t x1,
                                       uint32_t& o0, uint32_t& o1) {
    uint32_t ks2 = k0 ^ k1 ^ 0x1BD11BDAu;
    x0 += k0; x1 += k1;
#define TF_R(r) { x0 += x1; x1 = rotl32(x1, r); x1 ^= x0; }
    TF_R(13) TF_R(15) TF_R(26) TF_R(6)
    x0 += k1; x1 += ks2 + 1u;
    TF_R(17) TF_R(29) TF_R(16) TF_R(24)
    x0 += ks2; x1 += k0 + 2u;
    TF_R(13) TF_R(15) TF_R(26) TF_R(6)
    x0 += k0; x1 += k1 + 3u;
    TF_R(17) TF_R(29) TF_R(16) TF_R(24)
    x0 += k1; x1 += ks2 + 4u;
    TF_R(13) TF_R(15) TF_R(26) TF_R(6)
    x0 += ks2; x1 += k0 + 5u;
#undef TF_R
    o0 = x0; o1 = x1;
}

__device__ __forceinline__ uint32_t rbits32(uint32_t ka, uint32_t kb, uint32_t i) {
    uint32_t a, b;
    tf2x32(ka, kb, 0u, i, a, b);
    return a ^ b;
}

// ---------------- f32x2 packed helpers (sm_103a) ----------------------------
__device__ __forceinline__ unsigned long long pk2(float lo, float hi) {
    unsigned long long r;
    asm("mov.b64 %0, {%1, %2};" : "=l"(r) : "f"(lo), "f"(hi));
    return r;
}
__device__ __forceinline__ void upk2(unsigned long long v, float& lo, float& hi) {
    asm("mov.b64 {%0, %1}, %2;" : "=f"(lo), "=f"(hi) : "l"(v));
}
__device__ __forceinline__ unsigned long long add2(unsigned long long a,
                                                   unsigned long long b) {
    unsigned long long r;
    asm("add.rn.f32x2 %0, %1, %2;" : "=l"(r) : "l"(a), "l"(b));
    return r;
}
__device__ __forceinline__ unsigned long long mul2(unsigned long long a,
                                                   unsigned long long b) {
    unsigned long long r;
    asm("mul.rn.f32x2 %0, %1, %2;" : "=l"(r) : "l"(a), "l"(b));
    return r;
}

// ---------------- cluster helpers ------------------------------------------
__device__ __forceinline__ uint32_t smem_u32(const void* p) {
    uint32_t a;
    asm("{ .reg .u64 t; cvta.to.shared.u64 t, %1; cvt.u32.u64 %0, t; }"
        : "=r"(a) : "l"(p));
    return a;
}

__device__ __forceinline__ void mbar_wait_cluster(uint32_t mbar, uint32_t parity) {
    asm volatile(
        "{\n\t.reg .pred P;\n"
        "W_%=:\n\t"
        "mbarrier.try_wait.parity.acquire.cluster.shared::cta.b64 P, [%0], %1, 0x989680;\n\t"
        "@!P bra W_%=;\n\t}"
        :: "r"(mbar), "r"(parity) : "memory");
}

// ---------------- kernel 1: transpose x [B,C,N] -> [B,N,C] -----------------
__global__ void transpose_kernel(const float* __restrict__ x) {
    __shared__ float t[32][33];
    int b  = blockIdx.z;
    int n0 = blockIdx.x * 32;
    int c0 = blockIdx.y * 32;
    int tx = threadIdx.x, ty = threadIdx.y;   // (32, 8)
#pragma unroll
    for (int r = 0; r < 32; r += 8)
        t[ty + r][tx] = x[((size_t)b * CC + c0 + ty + r) * NN + n0 + tx];
    __syncthreads();
#pragma unroll
    for (int r = 0; r < 32; r += 8)
        g_xT[((size_t)b * NN + n0 + ty + r) * CC + c0 + tx] = t[tx][ty + r];
}

// ---------------- kernel 2: 2-CTA cluster FPS + permutation ----------------
// Grid = 24 CTAs, cluster (2,1,1).
//   CTAs 0-15: 8 FPS clusters, one batch each, half the points per CTA,
//              full coordinate copy in each CTA's smem, 8B/step DSMEM exchange.
//   CTAs 16-23: independent permutation, batch = blockIdx.x - 16 (no DSMEM).
__device__ __forceinline__ void bitonic8192(unsigned long long* s, int tid) {
    for (int k = 2; k <= 8192; k <<= 1) {
        for (int j = k >> 1; j > 0; j >>= 1) {
            __syncthreads();
            for (int t = tid; t < 8192; t += STHR) {
                int ixj = t ^ j;
                if (ixj > t) {
                    unsigned long long a = s[t], b = s[ixj];
                    bool up = ((t & k) == 0);
                    if ((a > b) == up) { s[t] = b; s[ixj] = a; }
                }
            }
        }
    }
    __syncthreads();
}

__global__ void __launch_bounds__(STHR, 1) __cluster_dims__(2, 1, 1)
sample_kernel(const float* __restrict__ pos) {
    extern __shared__ unsigned char s_raw[];
    __shared__ uint32_t s_val[16];
    __shared__ uint32_t s_id[16];
    __shared__ unsigned long long s_slot[2][2];   // [parity][rank]
    __shared__ float s_ctr[3];
    __shared__ unsigned long long s_mbar;
    __shared__ uint32_t skey[2];

    int tid  = threadIdx.x;
    int lane = tid & 31, wid = tid >> 5;

    if (blockIdx.x < 2 * BB) {
        // ---------------- FPS: batch b, rank r in 2-CTA cluster -------------
        int b    = blockIdx.x >> 1;
        int rank = blockIdx.x & 1;
        int peer = rank ^ 1;
        uint32_t mbar_a = smem_u32(&s_mbar);

        float* px = (float*)s_raw;     // full 8192-pt copy (coordinate lookup)
        float* py = px + NN;
        float* pz = py + NN;

        const float* pb = pos + (size_t)b * 3 * NN;
        for (int i = tid; i < NN; i += STHR) {
            px[i] = pb[i];
            py[i] = pb[NN + i];
            pz[i] = pb[2 * NN + i];
        }

        if (tid == 0) {
            asm volatile("mbarrier.init.shared.b64 [%0], %1;"
                         :: "r"(mbar_a), "r"(2u) : "memory");
            uint32_t ka, kb; tf2x32(0u, 42u, 0u, (uint32_t)b, ka, kb);
            uint32_t k2a, k2b; tf2x32(ka, kb, 0u, 1u, k2a, k2b);
            int start = (int)(rbits32(k2a, k2b, 0u) & (NN - 1));
            if (rank == 0) g_idx[b * MM + 0] = start;
            s_ctr[0] = start; // stash idx; coords read after syncthreads
        }
        __syncthreads();
        {
            int start = (int)s_ctr[0];
            if (tid == 0) {
                s_ctr[0] = px[start]; s_ctr[1] = py[start]; s_ctr[2] = pz[start];
            }
        }
        __syncthreads();
        // mbarrier visible cluster-wide before any remote arrive
        asm volatile("barrier.cluster.arrive.aligned;" ::: "memory");
        asm volatile("barrier.cluster.wait.aligned;" ::: "memory");

        // own half resident in registers: global idx = rank*HALF + tid + k*512
        int base = rank * HALF;
        unsigned long long qx[FPRS], qy[FPRS], qz[FPRS];
        float dm[FPT];
#pragma unroll
        for (int p = 0; p < FPRS; p++) {
            int i0 = base + tid + (2 * p) * STHR;
            int i1 = base + tid + (2 * p + 1) * STHR;
            qx[p] = pk2(px[i0], px[i1]);
            qy[p] = pk2(py[i0], py[i1]);
            qz[p] = pk2(pz[i0], pz[i1]);
            dm[2 * p] = 1e10f; dm[2 * p + 1] = 1e10f;
        }
        float cx = s_ctr[0], cy = s_ctr[1], cz = s_ctr[2];

        for (int s = 1; s < FPSM; s++) {
            int par = (s - 1) & 1;
            unsigned long long ncx = pk2(-cx, -cx);
            unsigned long long ncy = pk2(-cy, -cy);
            unsigned long long ncz = pk2(-cz, -cz);
            float best = -1.0f; int bi = 0x7fffffff;
#pragma unroll
            for (int p = 0; p < FPRS; p++) {
                unsigned long long dx = add2(qx[p], ncx);
                unsigned long long dy = add2(qy[p], ncy);
                unsigned long long dz = add2(qz[p], ncz);
                unsigned long long ss = add2(add2(mul2(dx, dx), mul2(dy, dy)),
                                             mul2(dz, dz));
                float d0, d1; upk2(ss, d0, d1);
                d0 = fminf(dm[2 * p], d0);     dm[2 * p] = d0;
                d1 = fminf(dm[2 * p + 1], d1); dm[2 * p + 1] = d1;
                // ascending global index order preserves first-index tie-break
                if (d0 > best) { best = d0; bi = base + tid + (2 * p) * STHR; }
                if (d1 > best) { best = d1; bi = base + tid + (2 * p + 1) * STHR; }
            }
            // stage 1: warp argmax (max bits, min index among ties)
            uint32_t bb   = __float_as_uint(best);
            uint32_t wmax = __reduce_max_sync(FULLMASK, bb);
            uint32_t cand = (bb == wmax) ? (uint32_t)bi : 0xffffffffu;
            uint32_t widx = __reduce_min_sync(FULLMASK, cand);
            if (lane == 0) { s_val[wid] = wmax; s_id[wid] = widx; }
            __syncthreads();
            // stage 2: warp 0 reduces 16 entries, exchanges 8B with peer CTA
            if (wid == 0) {
                uint32_t v  = (lane < 16) ? s_val[lane] : 0u;
                uint32_t ii = (lane < 16) ? s_id[lane] : 0xffffffffu;
                uint32_t m2 = __reduce_max_sync(FULLMASK, v);
                uint32_t c2 = (v == m2) ? ii : 0xffffffffu;
                uint32_t gi = __reduce_min_sync(FULLMASK, c2);
                if (lane == 0) {
                    unsigned long long pkd =
                        ((unsigned long long)m2 << 32) | (uint32_t)(~gi);
                    s_slot[par][rank] = pkd;                 // local slot
                    uint32_t la = smem_u32(&s_slot[par][rank]);
                    uint32_t ra, rm;
                    asm volatile("mapa.shared::cluster.u32 %0, %1, %2;"
                                 : "=r"(ra) : "r"(la), "r"(peer));
                    asm volatile("st.shared::cluster.u64 [%0], %1;"
                                 :: "r"(ra), "l"(pkd) : "memory");
                    asm volatile("mapa.shared::cluster.u32 %0, %1, %2;"
                                 : "=r"(rm) : "r"(mbar_a), "r"(peer));
                    asm volatile(
                        "mbarrier.arrive.release.cluster.shared::cluster.b64 _, [%0];"
                        :: "r"(rm) : "memory");
                    asm volatile("mbarrier.arrive.shared.b64 _, [%0];"
                                 :: "r"(mbar_a) : "memory");
                }
            }
            mbar_wait_cluster(mbar_a, (uint32_t)par);
            // final: u64 max of the two slots = exact (max value, min index)
            unsigned long long w0 = s_slot[par][0];
            unsigned long long w1 = s_slot[par][1];
            unsigned long long w  = (w0 > w1) ? w0 : w1;
            uint32_t gi = ~(uint32_t)w;
            if (rank == 0 && tid == 0) g_idx[b * MM + s] = (int)gi;
            cx = px[gi]; cy = py[gi]; cz = pz[gi];
        }
        // peers may have in-flight remote ops targeting this CTA
        asm volatile("barrier.cluster.arrive.aligned;" ::: "memory");
        asm volatile("barrier.cluster.wait.aligned;" ::: "memory");
    } else {
        // ---------------- permutation for batch bb (no cluster ops) --------
        int bb = blockIdx.x - 2 * BB;
        unsigned long long* comp = (unsigned long long*)s_raw;   // [8192]
        uint32_t* val1 = (uint32_t*)(comp + NN);                 // [8192]

        if (tid == 0) {
            uint32_t ra, rb; tf2x32(0u, 42u, 0u, 1u, ra, rb);          // fold_in(root,1)
            uint32_t ka, kb; tf2x32(ra, rb, 0u, (uint32_t)bb, ka, kb); // rkeys[bb]
            skey[0] = ka; skey[1] = kb;
        }
        __syncthreads();

        for (int round = 0; round < 2; round++) {
            uint32_t ka = skey[0], kb = skey[1];
            uint32_t na, nb, sa, sb;
            tf2x32(ka, kb, 0u, 0u, na, nb);   // next key
            tf2x32(ka, kb, 0u, 1u, sa, sb);   // subkey
            for (int i = tid; i < NN; i += STHR) {
                uint32_t bits = rbits32(sa, sb, (uint32_t)i);
                comp[i] = ((unsigned long long)bits << 32) | (unsigned)i; // stable
            }
            __syncthreads();
            if (tid == 0) { skey[0] = na; skey[1] = nb; }
            bitonic8192(comp, tid);
            if (round == 0) {
                for (int i = tid; i < NN; i += STHR) val1[i] = (uint32_t)comp[i];
                __syncthreads();
            } else {
                for (int i = tid; i < RANDM; i += STHR)
                    g_idx[bb * MM + FPSM + i] = (int)val1[(uint32_t)comp[i]];
            }
        }
    }
}

// ---------------- kernel 3: brute-force KNN (top-16 set) + pos_sub ---------
__global__ void __launch_bounds__(128, 1) knn_kernel(const float* __restrict__ pos,
                                                     float* __restrict__ out) {
    extern __shared__ float4 pts[];
    int b     = blockIdx.x >> 4;
    int chunk = blockIdx.x & 15;
    const float* pb = pos + (size_t)b * 3 * NN;
    for (int i = threadIdx.x; i < NN; i += 128) {
        float x = pb[i], y = pb[NN + i], z = pb[2 * NN + i];
        float sa = __fadd_rn(__fadd_rn(__fmul_rn(x, x), __fmul_rn(y, y)),
                             __fmul_rn(z, z));
        pts[i] = make_float4(x, y, z, sa);
    }
    __syncthreads();

    int m    = chunk * 128 + threadIdx.x;
    int cidx = g_idx[b * MM + m];
    float4 c = pts[cidx];
    float ss = c.w;

    float d16[KK]; int i16[KK];
#pragma unroll
    for (int s = 0; s < KK; s++) { d16[s] = 3.4e38f; i16[s] = 0; }
    float thresh = 3.4e38f;

#pragma unroll 4
    for (int n = 0; n < NN; n++) {
        float4 p = pts[n];
        float dot = __fmul_rn(c.x, p.x);
        dot = __fmaf_rn(c.y, p.y, dot);
        dot = __fmaf_rn(c.z, p.z, dot);
        float d2 = __fsub_rn(__fadd_rn(ss, p.w), __fmul_rn(2.0f, dot));
        if (d2 < thresh) {
            float mv = -3.4e38f; int ms = 0;
#pragma unroll
            for (int s = 0; s < KK; s++) if (d16[s] > mv) { mv = d16[s]; ms = s; }
#pragma unroll
            for (int s = 0; s < KK; s++) if (s == ms) { d16[s] = d2; i16[s] = n; }
            mv = -3.4e38f;
#pragma unroll
            for (int s = 0; s < KK; s++) mv = fmaxf(mv, d16[s]);
            thresh = mv;
        }
    }
#pragma unroll
    for (int s = 0; s < KK; s++) g_knn[((size_t)b * MM + m) * KK + s] = i16[s];

    float* psub = out + (size_t)BB * CC * MM;
    psub[((size_t)b * 3 + 0) * MM + m] = c.x;
    psub[((size_t)b * 3 + 1) * MM + m] = c.y;
    psub[((size_t)b * 3 + 2) * MM + m] = c.z;
}

// ---------------- kernel 4: softmax weights + weighted gather-sum ----------
__global__ void __launch_bounds__(256) out_kernel(const float* __restrict__ pos,
                                                  float* __restrict__ out) {
    __shared__ float tile[64 * 33];
    int bid  = blockIdx.x;              // 512 blocks = B * 64 tiles
    int b    = bid >> 6;
    int m0   = (bid & 63) * 32;
    int lane = threadIdx.x & 31, w = threadIdx.x >> 5;
    const float* pb = pos + (size_t)b * 3 * NN;
    const float* xb = g_xT + (size_t)b * NN * CC;

#pragma unroll 1
    for (int r = 0; r < 4; r++) {
        int cm = w * 4 + r;
        int m  = m0 + cm;
        int cidx = g_idx[b * MM + m];
        float cx = pb[cidx], cy = pb[NN + cidx], cz = pb[2 * NN + cidx];
        int nk = g_knn[((size_t)b * MM + m) * KK + (lane & 15)];
        float nx = pb[nk], ny = pb[NN + nk], nz = pb[2 * NN + nk];
        float dx = __fsub_rn(nx, cx), dy = __fsub_rn(ny, cy), dz = __fsub_rn(nz, cz);
        float d  = sqrtf(__fadd_rn(__fadd_rn(__fmul_rn(dx, dx), __fmul_rn(dy, dy)),
                                   __fmul_rn(dz, dz)));
        d = fmaxf(d, 1e-6f);
        float t = -__fdiv_rn(d, 0.2f);
        float tm = t;
#pragma unroll
        for (int o = 8; o > 0; o >>= 1) tm = fmaxf(tm, __shfl_xor_sync(FULLMASK, tm, o, 16));
        float e = expf(__fsub_rn(t, tm));
        float sum = 0.0f;
#pragma unroll
        for (int k = 0; k < KK; k++)
            sum = __fadd_rn(sum, __shfl_sync(FULLMASK, e, k, 16));
        float wgt = __fdiv_rn(e, sum);

        float a0 = 0.0f, a1 = 0.0f;
#pragma unroll
        for (int k = 0; k < KK; k++) {
            float wk = __shfl_sync(FULLMASK, wgt, k, 16);
            int   nn = __shfl_sync(FULLMASK, nk, k, 16);
            const float* row = xb + (size_t)nn * CC;
            a0 = __fadd_rn(a0, __fmul_rn(row[lane],      wk));
            a1 = __fadd_rn(a1, __fmul_rn(row[lane + 32], wk));
        }
        tile[lane * 33 + cm]        = a0;
        tile[(lane + 32) * 33 + cm] = a1;
    }
    __syncthreads();
    for (int e = threadIdx.x; e < 2048; e += 256) {
        int cch = e >> 5, mm = e & 31;
        out[((size_t)b * CC + cch) * MM + m0 + mm] = tile[cch * 33 + mm];
    }
}

// ---------------- launch ----------------------------------------------------
extern "C" void kernel_launch(void* const* d_in, const int* in_sizes, int n_in,
                              void* d_out, int out_size) {
    const float* x   = (const float*)d_in[0];
    const float* pos = (const float*)d_in[1];
    float* out = (float*)d_out;

    const int sample_smem = NN * 8 + NN * 4;           // 98304 (both paths fit)
    const int knn_smem    = NN * (int)sizeof(float4);  // 131072
    cudaFuncSetAttribute(sample_kernel, cudaFuncAttributeMaxDynamicSharedMemorySize, sample_smem);
    cudaFuncSetAttribute(knn_kernel,    cudaFuncAttributeMaxDynamicSharedMemorySize, knn_smem);

    transpose_kernel<<<dim3(NN / 32, CC / 32, BB), dim3(32, 8)>>>(x);
    sample_kernel<<<3 * BB, STHR, sample_smem>>>(pos);   // 16 FPS + 8 perm CTAs
    knn_kernel<<<128, 128, knn_smem>>>(pos, out);
    out_kernel<<<512, 256>>>(pos, out);
}

// round 8
// speedup vs baseline: 1.2055x; 1.2055x over previous
#include <cuda_runtime.h>
#include <cstdint>
#include <cstddef>

#define BB 8
#define CC 64
#define NN 8192
#define MM 2048
#define KK 16
#define FPSM 1433
#define RANDM 615
#define FULLMASK 0xffffffffu

#define STHR 512
#define PT   (NN / STHR)   // 16 points per thread
#define PRS  (PT / 2)      // 8 packed pairs per thread

// ---------------- device scratch (static: no allocations allowed) ----------
__device__ int   g_idx[BB * MM];                 // selected center indices
__device__ int   g_knn[BB * MM * KK];            // knn indices
__device__ float g_xT[(size_t)BB * NN * CC];     // x transposed to [B,N,C]

// ---------------- Threefry-2x32 (exact JAX) --------------------------------
__device__ __forceinline__ uint32_t rotl32(uint32_t v, int d) {
    return (v << d) | (v >> (32 - d));
}

__device__ __forceinline__ void tf2x32(uint32_t k0, uint32_t k1,
                                       uint32_t x0, uint32_t x1,
                                       uint32_t& o0, uint32_t& o1) {
    uint32_t ks2 = k0 ^ k1 ^ 0x1BD11BDAu;
    x0 += k0; x1 += k1;
#define TF_R(r) { x0 += x1; x1 = rotl32(x1, r); x1 ^= x0; }
    TF_R(13) TF_R(15) TF_R(26) TF_R(6)
    x0 += k1; x1 += ks2 + 1u;
    TF_R(17) TF_R(29) TF_R(16) TF_R(24)
    x0 += ks2; x1 += k0 + 2u;
    TF_R(13) TF_R(15) TF_R(26) TF_R(6)
    x0 += k0; x1 += k1 + 3u;
    TF_R(17) TF_R(29) TF_R(16) TF_R(24)
    x0 += k1; x1 += ks2 + 4u;
    TF_R(13) TF_R(15) TF_R(26) TF_R(6)
    x0 += ks2; x1 += k0 + 5u;
#undef TF_R
    o0 = x0; o1 = x1;
}

__device__ __forceinline__ uint32_t rbits32(uint32_t ka, uint32_t kb, uint32_t i) {
    uint32_t a, b;
    tf2x32(ka, kb, 0u, i, a, b);
    return a ^ b;
}

// ---------------- f32x2 packed helpers (sm_103a) ----------------------------
__device__ __forceinline__ unsigned long long pk2(float lo, float hi) {
    unsigned long long r;
    asm("mov.b64 %0, {%1, %2};" : "=l"(r) : "f"(lo), "f"(hi));
    return r;
}
__device__ __forceinline__ void upk2(unsigned long long v, float& lo, float& hi) {
    asm("mov.b64 {%0, %1}, %2;" : "=f"(lo), "=f"(hi) : "l"(v));
}
__device__ __forceinline__ unsigned long long add2(unsigned long long a,
                                                   unsigned long long b) {
    unsigned long long r;
    asm("add.rn.f32x2 %0, %1, %2;" : "=l"(r) : "l"(a), "l"(b));
    return r;
}
__device__ __forceinline__ unsigned long long mul2(unsigned long long a,
                                                   unsigned long long b) {
    unsigned long long r;
    asm("mul.rn.f32x2 %0, %1, %2;" : "=l"(r) : "l"(a), "l"(b));
    return r;
}

// ---------------- kernel 1: transpose x [B,C,N] -> [B,N,C] -----------------
__global__ void transpose_kernel(const float* __restrict__ x) {
    __shared__ float t[32][33];
    int b  = blockIdx.z;
    int n0 = blockIdx.x * 32;
    int c0 = blockIdx.y * 32;
    int tx = threadIdx.x, ty = threadIdx.y;   // (32, 8)
#pragma unroll
    for (int r = 0; r < 32; r += 8)
        t[ty + r][tx] = x[((size_t)b * CC + c0 + ty + r) * NN + n0 + tx];
    __syncthreads();
#pragma unroll
    for (int r = 0; r < 32; r += 8)
        g_xT[((size_t)b * NN + n0 + ty + r) * CC + c0 + tx] = t[tx][ty + r];
}

// ---------------- kernel 2: FPS (blocks 0-7) + permutation (blocks 8-15) ---
__device__ __forceinline__ void bitonic8192(unsigned long long* s, int tid) {
    for (int k = 2; k <= 8192; k <<= 1) {
        for (int j = k >> 1; j > 0; j >>= 1) {
            __syncthreads();
            for (int t = tid; t < 8192; t += STHR) {
                int ixj = t ^ j;
                if (ixj > t) {
                    unsigned long long a = s[t], b = s[ixj];
                    bool up = ((t & k) == 0);
                    if ((a > b) == up) { s[t] = b; s[ixj] = a; }
                }
            }
        }
    }
    __syncthreads();
}

__global__ void __launch_bounds__(STHR, 1) sample_kernel(const float* __restrict__ pos) {
    extern __shared__ unsigned char s_raw[];
    __shared__ unsigned long long s_pair[2][16];   // (val<<32 | ~idx) per warp, by parity
    __shared__ float s_ctr[3];
    __shared__ uint32_t skey[2];
    int bid = blockIdx.x;
    int tid = threadIdx.x;
    int lane = tid & 31, wid = tid >> 5;

    if (bid < BB) {
        // ---------------- FPS for batch bid ----------------
        float* px = (float*)s_raw;
        float* py = px + NN;
        float* pz = py + NN;

        const float* pb = pos + (size_t)bid * 3 * NN;
        for (int i = tid; i < NN; i += STHR) {
            px[i] = pb[i];
            py[i] = pb[NN + i];
            pz[i] = pb[2 * NN + i];
        }
        __syncthreads();

        if (tid == 0) {
            uint32_t ka, kb; tf2x32(0u, 42u, 0u, (uint32_t)bid, ka, kb);
            uint32_t k2a, k2b; tf2x32(ka, kb, 0u, 1u, k2a, k2b);
            int start = (int)(rbits32(k2a, k2b, 0u) & (NN - 1));
            g_idx[bid * MM + 0] = start;
            s_ctr[0] = px[start]; s_ctr[1] = py[start]; s_ctr[2] = pz[start];
        }
        __syncthreads();

        // pack resident points: pair p covers indices tid+2p*512 (lo), tid+(2p+1)*512 (hi)
        unsigned long long qx[PRS], qy[PRS], qz[PRS];
        float dm[PT];
#pragma unroll
        for (int p = 0; p < PRS; p++) {
            int i0 = tid + (2 * p) * STHR, i1 = tid + (2 * p + 1) * STHR;
            qx[p] = pk2(px[i0], px[i1]);
            qy[p] = pk2(py[i0], py[i1]);
            qz[p] = pk2(pz[i0], pz[i1]);
            dm[2 * p] = 1e10f; dm[2 * p + 1] = 1e10f;
        }
        float cx = s_ctr[0], cy = s_ctr[1], cz = s_ctr[2];

        for (int s = 1; s < FPSM; s++) {
            int par = s & 1;
            // rn(q + (-c)) == rn(q - c) exactly
            unsigned long long ncx = pk2(-cx, -cx);
            unsigned long long ncy = pk2(-cy, -cy);
            unsigned long long ncz = pk2(-cz, -cz);
            float best = -1.0f; int bi = 0x7fffffff;
#pragma unroll
            for (int p = 0; p < PRS; p++) {
                unsigned long long dx = add2(qx[p], ncx);
                unsigned long long dy = add2(qy[p], ncy);
                unsigned long long dz = add2(qz[p], ncz);
                unsigned long long ss = add2(add2(mul2(dx, dx), mul2(dy, dy)),
                                             mul2(dz, dz));
                float d0, d1; upk2(ss, d0, d1);
                d0 = fminf(dm[2 * p], d0);     dm[2 * p] = d0;
                d1 = fminf(dm[2 * p + 1], d1); dm[2 * p + 1] = d1;
                // ascending index order preserves first-index tie-break
                if (d0 > best) { best = d0; bi = tid + (2 * p) * STHR; }
                if (d1 > best) { best = d1; bi = tid + (2 * p + 1) * STHR; }
            }
            // warp argmax: max on bits (d>=0 -> monotone), min index among ties.
            // pack (val<<32 | ~idx): u64 max == (max val, min idx) exactly.
            uint32_t bb   = __float_as_uint(best);
            uint32_t wmax = __reduce_max_sync(FULLMASK, bb);
            uint32_t cand = (bb == wmax) ? ~(uint32_t)bi : 0u;
            uint32_t wnid = __reduce_max_sync(FULLMASK, cand);   // max(~idx) = min idx
            if (lane == 0)
                s_pair[par][wid] = ((unsigned long long)wmax << 32) | wnid;
            __syncthreads();
            // every warp reduces the 16 warp-winners redundantly (no 2nd barrier)
            unsigned long long e = s_pair[par][lane & 15];
            uint32_t v   = (uint32_t)(e >> 32);
            uint32_t ni  = (uint32_t)e;
            uint32_t m   = __reduce_max_sync(FULLMASK, v);
            uint32_t c2  = (v == m) ? ni : 0u;
            uint32_t gni = __reduce_max_sync(FULLMASK, c2);
            uint32_t gi  = ~gni;
            if (tid == 0) g_idx[bid * MM + s] = (int)gi;
            cx = px[gi]; cy = py[gi]; cz = pz[gi];
        }
    } else {
        // ---------------- permutation tail for batch bb ----------------
        int bb = bid - BB;
        unsigned long long* comp = (unsigned long long*)s_raw;   // [8192]
        uint32_t* val1 = (uint32_t*)(comp + NN);                 // [8192]

        if (tid == 0) {
            uint32_t ra, rb; tf2x32(0u, 42u, 0u, 1u, ra, rb);          // fold_in(root,1)
            uint32_t ka, kb; tf2x32(ra, rb, 0u, (uint32_t)bb, ka, kb); // rkeys[bb]
            skey[0] = ka; skey[1] = kb;
        }
        __syncthreads();

        for (int round = 0; round < 2; round++) {
            uint32_t ka = skey[0], kb = skey[1];
            uint32_t na, nb, sa, sb;
            tf2x32(ka, kb, 0u, 0u, na, nb);   // next key
            tf2x32(ka, kb, 0u, 1u, sa, sb);   // subkey
            for (int i = tid; i < NN; i += STHR) {
                uint32_t bits = rbits32(sa, sb, (uint32_t)i);
                comp[i] = ((unsigned long long)bits << 32) | (unsigned)i; // stable
            }
            __syncthreads();
            if (tid == 0) { skey[0] = na; skey[1] = nb; }
            bitonic8192(comp, tid);
            if (round == 0) {
                for (int i = tid; i < NN; i += STHR) val1[i] = (uint32_t)comp[i];
                __syncthreads();
            } else {
                for (int i = tid; i < RANDM; i += STHR)
                    g_idx[bb * MM + FPSM + i] = (int)val1[(uint32_t)comp[i]];
            }
        }
    }
}

// ---------------- kernel 3: brute-force KNN (top-16 set) + pos_sub ---------
__global__ void __launch_bounds__(128, 1) knn_kernel(const float* __restrict__ pos,
                                                     float* __restrict__ out) {
    extern __shared__ float4 pts[];
    int b     = blockIdx.x >> 4;
    int chunk = blockIdx.x & 15;
    const float* pb = pos + (size_t)b * 3 * NN;
    for (int i = threadIdx.x; i < NN; i += 128) {
        float x = pb[i], y = pb[NN + i], z = pb[2 * NN + i];
        float sa = __fadd_rn(__fadd_rn(__fmul_rn(x, x), __fmul_rn(y, y)),
                             __fmul_rn(z, z));
        pts[i] = make_float4(x, y, z, sa);
    }
    __syncthreads();

    int m    = chunk * 128 + threadIdx.x;
    int cidx = g_idx[b * MM + m];
    float4 c = pts[cidx];
    float ss = c.w;

    float d16[KK]; int i16[KK];
#pragma unroll
    for (int s = 0; s < KK; s++) { d16[s] = 3.4e38f; i16[s] = 0; }
    float thresh = 3.4e38f;

    // unroll 8: batch loads for MLP (1 block/SM -> latency-bound otherwise)
#pragma unroll 1
    for (int n0 = 0; n0 < NN; n0 += 8) {
        float d2v[8];
#pragma unroll
        for (int u = 0; u < 8; u++) {
            float4 p = pts[n0 + u];
            float dot = __fmul_rn(c.x, p.x);
            dot = __fmaf_rn(c.y, p.y, dot);
            dot = __fmaf_rn(c.z, p.z, dot);
            d2v[u] = __fsub_rn(__fadd_rn(ss, p.w), __fmul_rn(2.0f, dot));
        }
#pragma unroll
        for (int u = 0; u < 8; u++) {
            float d2 = d2v[u];
            if (d2 < thresh) {
                int n = n0 + u;
                float mv = -3.4e38f; int ms = 0;
#pragma unroll
                for (int s = 0; s < KK; s++) if (d16[s] > mv) { mv = d16[s]; ms = s; }
#pragma unroll
                for (int s = 0; s < KK; s++) if (s == ms) { d16[s] = d2; i16[s] = n; }
                mv = -3.4e38f;
#pragma unroll
                for (int s = 0; s < KK; s++) mv = fmaxf(mv, d16[s]);
                thresh = mv;
            }
        }
    }
#pragma unroll
    for (int s = 0; s < KK; s++) g_knn[((size_t)b * MM + m) * KK + s] = i16[s];

    float* psub = out + (size_t)BB * CC * MM;
    psub[((size_t)b * 3 + 0) * MM + m] = c.x;
    psub[((size_t)b * 3 + 1) * MM + m] = c.y;
    psub[((size_t)b * 3 + 2) * MM + m] = c.z;
}

// ---------------- kernel 4: softmax weights + weighted gather-sum ----------
__global__ void __launch_bounds__(256) out_kernel(const float* __restrict__ pos,
                                                  float* __restrict__ out) {
    __shared__ float tile[64 * 33];
    int bid  = blockIdx.x;              // 512 blocks = B * 64 tiles
    int b    = bid >> 6;
    int m0   = (bid & 63) * 32;
    int lane = threadIdx.x & 31, w = threadIdx.x >> 5;
    const float* pb = pos + (size_t)b * 3 * NN;
    const float* xb = g_xT + (size_t)b * NN * CC;

#pragma unroll 1
    for (int r = 0; r < 4; r++) {
        int cm = w * 4 + r;
        int m  = m0 + cm;
        int cidx = g_idx[b * MM + m];
        float cx = pb[cidx], cy = pb[NN + cidx], cz = pb[2 * NN + cidx];
        int nk = g_knn[((size_t)b * MM + m) * KK + (lane & 15)];
        float nx = pb[nk], ny = pb[NN + nk], nz = pb[2 * NN + nk];
        float dx = __fsub_rn(nx, cx), dy = __fsub_rn(ny, cy), dz = __fsub_rn(nz, cz);
        float d  = sqrtf(__fadd_rn(__fadd_rn(__fmul_rn(dx, dx), __fmul_rn(dy, dy)),
                                   __fmul_rn(dz, dz)));
        d = fmaxf(d, 1e-6f);
        float t = -__fdiv_rn(d, 0.2f);
        float tm = t;
#pragma unroll
        for (int o = 8; o > 0; o >>= 1) tm = fmaxf(tm, __shfl_xor_sync(FULLMASK, tm, o, 16));
        float e = expf(__fsub_rn(t, tm));
        float sum = 0.0f;
#pragma unroll
        for (int k = 0; k < KK; k++)
            sum = __fadd_rn(sum, __shfl_sync(FULLMASK, e, k, 16));
        float wgt = __fdiv_rn(e, sum);

        float a0 = 0.0f, a1 = 0.0f;
#pragma unroll
        for (int k = 0; k < KK; k++) {
            float wk = __shfl_sync(FULLMASK, wgt, k, 16);
            int   nn = __shfl_sync(FULLMASK, nk, k, 16);
            const float* row = xb + (size_t)nn * CC;
            a0 = __fadd_rn(a0, __fmul_rn(row[lane],      wk));
            a1 = __fadd_rn(a1, __fmul_rn(row[lane + 32], wk));
        }
        tile[lane * 33 + cm]        = a0;
        tile[(lane + 32) * 33 + cm] = a1;
    }
    __syncthreads();
    for (int e = threadIdx.x; e < 2048; e += 256) {
        int cch = e >> 5, mm = e & 31;
        out[((size_t)b * CC + cch) * MM + m0 + mm] = tile[cch * 33 + mm];
    }
}

// ---------------- launch ----------------------------------------------------
extern "C" void kernel_launch(void* const* d_in, const int* in_sizes, int n_in,
                              void* d_out, int out_size) {
    const float* x   = (const float*)d_in[0];
    const float* pos = (const float*)d_in[1];
    float* out = (float*)d_out;

    const int sample_smem = NN * 8 + NN * 4;           // 98304 (both paths fit)
    const int knn_smem    = NN * (int)sizeof(float4);  // 131072
    static bool attr_done = false;
    if (!attr_done) {
        cudaFuncSetAttribute(sample_kernel, cudaFuncAttributeMaxDynamicSharedMemorySize, sample_smem);
        cudaFuncSetAttribute(knn_kernel,    cudaFuncAttributeMaxDynamicSharedMemorySize, knn_smem);
        attr_done = true;
    }

    // Overlap transpose (feeds only out_kernel) with sample via forked stream.
    static cudaStream_t s2 = nullptr;
    static cudaEvent_t ev_fork = nullptr, ev_join = nullptr;
    if (!s2) {
        cudaStreamCreateWithFlags(&s2, cudaStreamNonBlocking);
        cudaEventCreateWithFlags(&ev_fork, cudaEventDisableTiming);
        cudaEventCreateWithFlags(&ev_join, cudaEventDisableTiming);
    }

    cudaStream_t s0 = 0;  // capture (legacy default) stream
    cudaEventRecord(ev_fork, s0);
    cudaStreamWaitEvent(s2, ev_fork, 0);

    transpose_kernel<<<dim3(NN / 32, CC / 32, BB), dim3(32, 8), 0, s2>>>(x);
    cudaEventRecord(ev_join, s2);

    sample_kernel<<<2 * BB, STHR, sample_smem, s0>>>(pos);
    knn_kernel<<<128, 128, knn_smem, s0>>>(pos, out);

    cudaStreamWaitEvent(s0, ev_join, 0);
    out_kernel<<<512, 256, 0, s0>>>(pos, out);
}

// round 9
// speedup vs baseline: 1.2484x; 1.0356x over previous
#include <cuda_runtime.h>
#include <cstdint>
#include <cstddef>

#define BB 8
#define CC 64
#define NN 8192
#define MM 2048
#define KK 16
#define FPSM 1433
#define RANDM 615
#define FULLMASK 0xffffffffu

#define STHR 512
#define PT   (NN / STHR)   // 16 points per thread
#define PRS  (PT / 2)      // 8 packed pairs per thread

// ---------------- device scratch (static: no allocations allowed) ----------
__device__ int   g_idx[BB * MM];                 // selected center indices
__device__ int   g_knn[BB * MM * KK];            // knn indices
__device__ float g_xT[(size_t)BB * NN * CC];     // x transposed to [B,N,C]

// ---------------- Threefry-2x32 (exact JAX) --------------------------------
__device__ __forceinline__ uint32_t rotl32(uint32_t v, int d) {
    return (v << d) | (v >> (32 - d));
}

__device__ __forceinline__ void tf2x32(uint32_t k0, uint32_t k1,
                                       uint32_t x0, uint32_t x1,
                                       uint32_t& o0, uint32_t& o1) {
    uint32_t ks2 = k0 ^ k1 ^ 0x1BD11BDAu;
    x0 += k0; x1 += k1;
#define TF_R(r) { x0 += x1; x1 = rotl32(x1, r); x1 ^= x0; }
    TF_R(13) TF_R(15) TF_R(26) TF_R(6)
    x0 += k1; x1 += ks2 + 1u;
    TF_R(17) TF_R(29) TF_R(16) TF_R(24)
    x0 += ks2; x1 += k0 + 2u;
    TF_R(13) TF_R(15) TF_R(26) TF_R(6)
    x0 += k0; x1 += k1 + 3u;
    TF_R(17) TF_R(29) TF_R(16) TF_R(24)
    x0 += k1; x1 += ks2 + 4u;
    TF_R(13) TF_R(15) TF_R(26) TF_R(6)
    x0 += ks2; x1 += k0 + 5u;
#undef TF_R
    o0 = x0; o1 = x1;
}

__device__ __forceinline__ uint32_t rbits32(uint32_t ka, uint32_t kb, uint32_t i) {
    uint32_t a, b;
    tf2x32(ka, kb, 0u, i, a, b);
    return a ^ b;
}

// ---------------- f32x2 packed helpers (sm_103a) ----------------------------
__device__ __forceinline__ unsigned long long pk2(float lo, float hi) {
    unsigned long long r;
    asm("mov.b64 %0, {%1, %2};" : "=l"(r) : "f"(lo), "f"(hi));
    return r;
}
__device__ __forceinline__ void upk2(unsigned long long v, float& lo, float& hi) {
    asm("mov.b64 {%0, %1}, %2;" : "=f"(lo), "=f"(hi) : "l"(v));
}
__device__ __forceinline__ unsigned long long add2(unsigned long long a,
                                                   unsigned long long b) {
    unsigned long long r;
    asm("add.rn.f32x2 %0, %1, %2;" : "=l"(r) : "l"(a), "l"(b));
    return r;
}
__device__ __forceinline__ unsigned long long mul2(unsigned long long a,
                                                   unsigned long long b) {
    unsigned long long r;
    asm("mul.rn.f32x2 %0, %1, %2;" : "=l"(r) : "l"(a), "l"(b));
    return r;
}

// ---------------- kernel 1: transpose x [B,C,N] -> [B,N,C] -----------------
__global__ void transpose_kernel(const float* __restrict__ x) {
    __shared__ float t[32][33];
    int b  = blockIdx.z;
    int n0 = blockIdx.x * 32;
    int c0 = blockIdx.y * 32;
    int tx = threadIdx.x, ty = threadIdx.y;   // (32, 8)
#pragma unroll
    for (int r = 0; r < 32; r += 8)
        t[ty + r][tx] = x[((size_t)b * CC + c0 + ty + r) * NN + n0 + tx];
    __syncthreads();
#pragma unroll
    for (int r = 0; r < 32; r += 8)
        g_xT[((size_t)b * NN + n0 + ty + r) * CC + c0 + tx] = t[tx][ty + r];
}

// ---------------- kernel 2: FPS (blocks 0-7) + permutation (blocks 8-15) ---
__device__ __forceinline__ void bitonic8192(unsigned long long* s, int tid) {
    for (int k = 2; k <= 8192; k <<= 1) {
        for (int j = k >> 1; j > 0; j >>= 1) {
            __syncthreads();
            for (int t = tid; t < 8192; t += STHR) {
                int ixj = t ^ j;
                if (ixj > t) {
                    unsigned long long a = s[t], b = s[ixj];
                    bool up = ((t & k) == 0);
                    if ((a > b) == up) { s[t] = b; s[ixj] = a; }
                }
            }
        }
    }
    __syncthreads();
}

__global__ void __launch_bounds__(STHR, 1) sample_kernel(const float* __restrict__ pos) {
    extern __shared__ unsigned char s_raw[];
    __shared__ unsigned long long s_pair[2][16];   // (val<<32 | idx) per warp, by parity
    __shared__ float s_ctr[3];
    __shared__ uint32_t skey[2];
    int bid = blockIdx.x;
    int tid = threadIdx.x;
    int lane = tid & 31, wid = tid >> 5;

    if (bid < BB) {
        // ---------------- FPS for batch bid ----------------
        float* px = (float*)s_raw;
        float* py = px + NN;
        float* pz = py + NN;

        const float* pb = pos + (size_t)bid * 3 * NN;
        for (int i = tid; i < NN; i += STHR) {
            px[i] = pb[i];
            py[i] = pb[NN + i];
            pz[i] = pb[2 * NN + i];
        }
        __syncthreads();

        if (tid == 0) {
            uint32_t ka, kb; tf2x32(0u, 42u, 0u, (uint32_t)bid, ka, kb);
            uint32_t k2a, k2b; tf2x32(ka, kb, 0u, 1u, k2a, k2b);
            int start = (int)(rbits32(k2a, k2b, 0u) & (NN - 1));
            g_idx[bid * MM + 0] = start;
            s_ctr[0] = px[start]; s_ctr[1] = py[start]; s_ctr[2] = pz[start];
        }
        __syncthreads();

        // pack resident points: pair p covers indices tid+2p*512 (lo), tid+(2p+1)*512 (hi)
        unsigned long long qx[PRS], qy[PRS], qz[PRS];
        float dm[PT];
#pragma unroll
        for (int p = 0; p < PRS; p++) {
            int i0 = tid + (2 * p) * STHR, i1 = tid + (2 * p + 1) * STHR;
            qx[p] = pk2(px[i0], px[i1]);
            qy[p] = pk2(py[i0], py[i1]);
            qz[p] = pk2(pz[i0], pz[i1]);
            dm[2 * p] = 1e10f; dm[2 * p + 1] = 1e10f;
        }
        float cx = s_ctr[0], cy = s_ctr[1], cz = s_ctr[2];

        for (int s = 1; s < FPSM; s++) {
            int par = s & 1;
            // rn(q + (-c)) == rn(q - c) exactly
            unsigned long long ncx = pk2(-cx, -cx);
            unsigned long long ncy = pk2(-cy, -cy);
            unsigned long long ncz = pk2(-cz, -cz);
            // hot loop: min-update only, NO index tracking
#pragma unroll
            for (int p = 0; p < PRS; p++) {
                unsigned long long dx = add2(qx[p], ncx);
                unsigned long long dy = add2(qy[p], ncy);
                unsigned long long dz = add2(qz[p], ncz);
                unsigned long long ss = add2(add2(mul2(dx, dx), mul2(dy, dy)),
                                             mul2(dz, dz));
                float d0, d1; upk2(ss, d0, d1);
                dm[2 * p]     = fminf(dm[2 * p],     d0);
                dm[2 * p + 1] = fminf(dm[2 * p + 1], d1);
            }
            // local max via fmax tree (exact: max is order-free)
            float t8[8];
#pragma unroll
            for (int k = 0; k < 8; k++) t8[k] = fmaxf(dm[k], dm[k + 8]);
#pragma unroll
            for (int k = 0; k < 4; k++) t8[k] = fmaxf(t8[k], t8[k + 4]);
            float best = fmaxf(fmaxf(t8[0], t8[1]), fmaxf(t8[2], t8[3]));

            // warp max on bits (d>=0 -> u32 monotone)
            uint32_t bb   = __float_as_uint(best);
            uint32_t wmax = __reduce_max_sync(FULLMASK, bb);
            // lazy index: only max-holding lanes scan for FIRST equal slot
            uint32_t cand = 0xffffffffu;
            if (bb == wmax) {
                int k = 15;
#pragma unroll
                for (int j = 14; j >= 0; j--) if (dm[j] == best) k = j;
                cand = (uint32_t)(tid + k * STHR);   // first k = smallest global idx
            }
            uint32_t widx = __reduce_min_sync(FULLMASK, cand);
            if (lane == 0)
                s_pair[par][wid] = ((unsigned long long)wmax << 32) | widx;
            __syncthreads();
            // every warp reduces the 16 warp-winners redundantly (no 2nd barrier)
            unsigned long long e = s_pair[par][lane & 15];
            uint32_t v   = (uint32_t)(e >> 32);
            uint32_t wi2 = (uint32_t)e;
            uint32_t m   = __reduce_max_sync(FULLMASK, v);
            uint32_t c2  = (v == m) ? wi2 : 0xffffffffu;
            uint32_t gi  = __reduce_min_sync(FULLMASK, c2);
            if (tid == 0) g_idx[bid * MM + s] = (int)gi;
            cx = px[gi]; cy = py[gi]; cz = pz[gi];
        }
    } else {
        // ---------------- permutation tail for batch bb ----------------
        int bb = bid - BB;
        unsigned long long* comp = (unsigned long long*)s_raw;   // [8192]
        uint32_t* val1 = (uint32_t*)(comp + NN);                 // [8192]

        if (tid == 0) {
            uint32_t ra, rb; tf2x32(0u, 42u, 0u, 1u, ra, rb);          // fold_in(root,1)
            uint32_t ka, kb; tf2x32(ra, rb, 0u, (uint32_t)bb, ka, kb); // rkeys[bb]
            skey[0] = ka; skey[1] = kb;
        }
        __syncthreads();

        for (int round = 0; round < 2; round++) {
            uint32_t ka = skey[0], kb = skey[1];
            uint32_t na, nb, sa, sb;
            tf2x32(ka, kb, 0u, 0u, na, nb);   // next key
            tf2x32(ka, kb, 0u, 1u, sa, sb);   // subkey
            for (int i = tid; i < NN; i += STHR) {
                uint32_t bits = rbits32(sa, sb, (uint32_t)i);
                comp[i] = ((unsigned long long)bits << 32) | (unsigned)i; // stable
            }
            __syncthreads();
            if (tid == 0) { skey[0] = na; skey[1] = nb; }
            bitonic8192(comp, tid);
            if (round == 0) {
                for (int i = tid; i < NN; i += STHR) val1[i] = (uint32_t)comp[i];
                __syncthreads();
            } else {
                for (int i = tid; i < RANDM; i += STHR)
                    g_idx[bb * MM + FPSM + i] = (int)val1[(uint32_t)comp[i]];
            }
        }
    }
}

// ---------------- kernel 3: brute-force KNN (top-16 set) + pos_sub ---------
__global__ void __launch_bounds__(128, 1) knn_kernel(const float* __restrict__ pos,
                                                     float* __restrict__ out) {
    extern __shared__ float4 pts[];
    int b     = blockIdx.x >> 4;
    int chunk = blockIdx.x & 15;
    const float* pb = pos + (size_t)b * 3 * NN;
    for (int i = threadIdx.x; i < NN; i += 128) {
        float x = pb[i], y = pb[NN + i], z = pb[2 * NN + i];
        float sa = __fadd_rn(__fadd_rn(__fmul_rn(x, x), __fmul_rn(y, y)),
                             __fmul_rn(z, z));
        pts[i] = make_float4(x, y, z, sa);
    }
    __syncthreads();

    int m    = chunk * 128 + threadIdx.x;
    int cidx = g_idx[b * MM + m];
    float4 c = pts[cidx];
    float ss = c.w;

    float d16[KK]; int i16[KK];
#pragma unroll
    for (int s = 0; s < KK; s++) { d16[s] = 3.4e38f; i16[s] = 0; }
    float thresh = 3.4e38f;

#pragma unroll 4
    for (int n = 0; n < NN; n++) {
        float4 p = pts[n];
        float dot = __fmul_rn(c.x, p.x);
        dot = __fmaf_rn(c.y, p.y, dot);
        dot = __fmaf_rn(c.z, p.z, dot);
        float d2 = __fsub_rn(__fadd_rn(ss, p.w), __fmul_rn(2.0f, dot));
        if (d2 < thresh) {
            float mv = -3.4e38f; int ms = 0;
#pragma unroll
            for (int s = 0; s < KK; s++) if (d16[s] > mv) { mv = d16[s]; ms = s; }
#pragma unroll
            for (int s = 0; s < KK; s++) if (s == ms) { d16[s] = d2; i16[s] = n; }
            mv = -3.4e38f;
#pragma unroll
            for (int s = 0; s < KK; s++) mv = fmaxf(mv, d16[s]);
            thresh = mv;
        }
    }
#pragma unroll
    for (int s = 0; s < KK; s++) g_knn[((size_t)b * MM + m) * KK + s] = i16[s];

    float* psub = out + (size_t)BB * CC * MM;
    psub[((size_t)b * 3 + 0) * MM + m] = c.x;
    psub[((size_t)b * 3 + 1) * MM + m] = c.y;
    psub[((size_t)b * 3 + 2) * MM + m] = c.z;
}

// ---------------- kernel 4: softmax weights + weighted gather-sum ----------
__global__ void __launch_bounds__(256) out_kernel(const float* __restrict__ pos,
                                                  float* __restrict__ out) {
    __shared__ float tile[64 * 33];
    int bid  = blockIdx.x;              // 512 blocks = B * 64 tiles
    int b    = bid >> 6;
    int m0   = (bid & 63) * 32;
    int lane = threadIdx.x & 31, w = threadIdx.x >> 5;
    const float* pb = pos + (size_t)b * 3 * NN;
    const float* xb = g_xT + (size_t)b * NN * CC;

#pragma unroll 1
    for (int r = 0; r < 4; r++) {
        int cm = w * 4 + r;
        int m  = m0 + cm;
        int cidx = g_idx[b * MM + m];
        float cx = pb[cidx], cy = pb[NN + cidx], cz = pb[2 * NN + cidx];
        int nk = g_knn[((size_t)b * MM + m) * KK + (lane & 15)];
        float nx = pb[nk], ny = pb[NN + nk], nz = pb[2 * NN + nk];
        float dx = __fsub_rn(nx, cx), dy = __fsub_rn(ny, cy), dz = __fsub_rn(nz, cz);
        float d  = sqrtf(__fadd_rn(__fadd_rn(__fmul_rn(dx, dx), __fmul_rn(dy, dy)),
                                   __fmul_rn(dz, dz)));
        d = fmaxf(d, 1e-6f);
        float t = -__fdiv_rn(d, 0.2f);
        float tm = t;
#pragma unroll
        for (int o = 8; o > 0; o >>= 1) tm = fmaxf(tm, __shfl_xor_sync(FULLMASK, tm, o, 16));
        float e = expf(__fsub_rn(t, tm));
        float sum = 0.0f;
#pragma unroll
        for (int k = 0; k < KK; k++)
            sum = __fadd_rn(sum, __shfl_sync(FULLMASK, e, k, 16));
        float wgt = __fdiv_rn(e, sum);

        float a0 = 0.0f, a1 = 0.0f;
#pragma unroll
        for (int k = 0; k < KK; k++) {
            float wk = __shfl_sync(FULLMASK, wgt, k, 16);
            int   nn = __shfl_sync(FULLMASK, nk, k, 16);
            const float* row = xb + (size_t)nn * CC;
            a0 = __fadd_rn(a0, __fmul_rn(row[lane],      wk));
            a1 = __fadd_rn(a1, __fmul_rn(row[lane + 32], wk));
        }
        tile[lane * 33 + cm]        = a0;
        tile[(lane + 32) * 33 + cm] = a1;
    }
    __syncthreads();
    for (int e = threadIdx.x; e < 2048; e += 256) {
        int cch = e >> 5, mm = e & 31;
        out[((size_t)b * CC + cch) * MM + m0 + mm] = tile[cch * 33 + mm];
    }
}

// ---------------- launch ----------------------------------------------------
extern "C" void kernel_launch(void* const* d_in, const int* in_sizes, int n_in,
                              void* d_out, int out_size) {
    const float* x   = (const float*)d_in[0];
    const float* pos = (const float*)d_in[1];
    float* out = (float*)d_out;

    const int sample_smem = NN * 8 + NN * 4;           // 98304 (both paths fit)
    const int knn_smem    = NN * (int)sizeof(float4);  // 131072
    cudaFuncSetAttribute(sample_kernel, cudaFuncAttributeMaxDynamicSharedMemorySize, sample_smem);
    cudaFuncSetAttribute(knn_kernel,    cudaFuncAttributeMaxDynamicSharedMemorySize, knn_smem);

    transpose_kernel<<<dim3(NN / 32, CC / 32, BB), dim3(32, 8)>>>(x);
    sample_kernel<<<2 * BB, STHR, sample_smem>>>(pos);
    knn_kernel<<<128, 128, knn_smem>>>(pos, out);
    out_kernel<<<512, 256>>>(pos, out);
}